// round 5
// baseline (speedup 1.0000x reference)
#include <cuda_runtime.h>

typedef unsigned long long ull;

#define LOG2E_F  1.4426950408889634f
#define LOG2PI_F 1.8378770664093453f
#define LN2SQ_F  0.4804530139182014f
#define KCOMP 8
#define TPB 256
#define ELEMS_PER_THREAD 4
#define ELEMS_PER_BLOCK (TPB * ELEMS_PER_THREAD)  // 1024

// ---- packed f32x2 helpers (sm_100+ 64-bit fp32 pipe) ----
__device__ __forceinline__ ull pk2(float a, float b) {
    ull r; asm("mov.b64 %0, {%1, %2};" : "=l"(r) : "f"(a), "f"(b)); return r;
}
__device__ __forceinline__ void upk2(ull v, float& a, float& b) {
    asm("mov.b64 {%0, %1}, %2;" : "=f"(a), "=f"(b) : "l"(v));
}
__device__ __forceinline__ ull add2(ull a, ull b) {
    ull r; asm("add.rn.f32x2 %0, %1, %2;" : "=l"(r) : "l"(a), "l"(b)); return r;
}
__device__ __forceinline__ ull fma2(ull a, ull b, ull c) {
    ull r; asm("fma.rn.f32x2 %0, %1, %2, %3;" : "=l"(r) : "l"(a), "l"(b), "l"(c)); return r;
}
__device__ __forceinline__ float ex2f_fast(float x) {
    float r; asm("ex2.approx.ftz.f32 %0, %1;" : "=f"(r) : "f"(x)); return r;
}
__device__ __forceinline__ float rcpf_fast(float x) {
    float r; asm("rcp.approx.ftz.f32 %0, %1;" : "=f"(r) : "f"(x)); return r;
}
// packed exp2: unpack, two scalar EX2, repack
__device__ __forceinline__ ull ex2_pair(ull t) {
    float t0, t1; upk2(t, t0, t1);
    return pk2(ex2f_fast(t0), ex2f_fast(t1));
}

__global__ __launch_bounds__(TPB) void gmm_hscore_kernel(
    const float4* __restrict__ x4,
    const float*  __restrict__ mean,
    const float*  __restrict__ logvar,
    const float*  __restrict__ logweight,
    float4*       __restrict__ out4)
{
    // Per-k packed constants, paired for LDS.128:
    //   sAB[k] = {a2, b2}   exponent quadratic coeffs (base-2, weight folded)
    //   sCV[k] = {c2, nvs2} exponent constant + scaled -invvar
    __shared__ ulonglong2 sAB[KCOMP];
    __shared__ ulonglong2 sCV[KCOMP];

    const int t = threadIdx.x;
    if (t < KCOMP) {
        float lv = logvar[t];
        float mu = mean[t];
        float lw = logweight[t];
        float iv = ex2f_fast(-lv * LOG2E_F);           // exp(-lv) = 1/var
        float a  = -0.5f * iv * LOG2E_F;
        float b  = -2.0f * a * mu;
        float c  = fmaf(a, mu * mu, (lw - 0.5f * (lv + LOG2PI_F)) * LOG2E_F);
        float nvs = -iv * (1.0f / LN2SQ_F);
        sAB[t] = make_ulonglong2(pk2(a, a), pk2(b, b));
        sCV[t] = make_ulonglong2(pk2(c, c), pk2(nvs, nvs));
    }
    __syncthreads();

    // ---- load 4 elements (one coalesced float4) ----
    const int base = blockIdx.x * TPB + t;   // in float4 units
    float4 xa = x4[base];

    ull X0 = pk2(xa.x, xa.y);
    ull X1 = pk2(xa.z, xa.w);

    const ull Z = pk2(0.0f, 0.0f);
    ull MP0 = Z, MP1 = Z, MD0 = Z, MD1 = Z, DD0 = Z, DD1 = Z;

    // Per-warp rotation of the component order: breaks cross-warp lockstep so
    // EX2 (MUFU) bursts from different warps in an SMSP don't collide.
    const int rot = (t >> 5) & (KCOMP - 1);

    #pragma unroll
    for (int k = 0; k < KCOMP; k++) {
        int kk = k + rot;
        kk = (kk >= KCOMP) ? (kk - KCOMP) : kk;
        const ulonglong2 ab = sAB[kk];
        const ulonglong2 cv = sCV[kk];
        const ull a2 = ab.x, b2 = ab.y, c2 = cv.x, v2 = cv.y;

        ull H0 = fma2(a2, X0, b2);
        ull H1 = fma2(a2, X1, b2);
        ull T0 = fma2(H0, X0, c2);
        ull T1 = fma2(H1, X1, c2);
        ull P0 = ex2_pair(T0);                // weight*pdf
        ull P1 = ex2_pair(T1);
        ull S0 = fma2(a2, X0, H0);            // S' = 2a*x + b  (= S/ln2)
        ull S1 = fma2(a2, X1, H1);
        MP0 = add2(MP0, P0);
        MP1 = add2(MP1, P1);
        MD0 = fma2(P0, S0, MD0);
        MD1 = fma2(P1, S1, MD1);
        ull U0 = fma2(S0, S0, v2);            // S'^2 - iv/ln2^2
        ull U1 = fma2(S1, S1, v2);
        DD0 = fma2(P0, U0, DD0);
        DD1 = fma2(P1, U1, DD1);
    }

    // ---- epilogue: h = ln2^2 * ( -0.5*(md'/mp)^2 + dd'/mp ) ----
    float h[4];
    {
        float mp0, mp1, md0, md1, dd0, dd1;
        upk2(MP0, mp0, mp1); upk2(MD0, md0, md1); upk2(DD0, dd0, dd1);
        float r0 = rcpf_fast(mp0), r1 = rcpf_fast(mp1);
        float dl0 = md0 * r0,      dl1 = md1 * r1;
        h[0] = LN2SQ_F * fmaf(-0.5f * dl0, dl0, dd0 * r0);
        h[1] = LN2SQ_F * fmaf(-0.5f * dl1, dl1, dd1 * r1);
        upk2(MP1, mp0, mp1); upk2(MD1, md0, md1); upk2(DD1, dd0, dd1);
        r0 = rcpf_fast(mp0); r1 = rcpf_fast(mp1);
        dl0 = md0 * r0;      dl1 = md1 * r1;
        h[2] = LN2SQ_F * fmaf(-0.5f * dl0, dl0, dd0 * r0);
        h[3] = LN2SQ_F * fmaf(-0.5f * dl1, dl1, dd1 * r1);
    }

    out4[base] = make_float4(h[0], h[1], h[2], h[3]);
}

extern "C" void kernel_launch(void* const* d_in, const int* in_sizes, int n_in,
                              void* d_out, int out_size) {
    const float4* x4        = (const float4*)d_in[0];
    const float*  mean      = (const float*)d_in[1];
    const float*  logvar    = (const float*)d_in[2];
    const float*  logweight = (const float*)d_in[3];
    float4*       out4      = (float4*)d_out;

    int n = in_sizes[0];                      // 4194304, divisible by 1024
    int blocks = n / ELEMS_PER_BLOCK;         // 4096
    gmm_hscore_kernel<<<blocks, TPB>>>(x4, mean, logvar, logweight, out4);
}

// round 6
// speedup vs baseline: 1.1404x; 1.1404x over previous
#include <cuda_runtime.h>

typedef unsigned long long ull;

#define LOG2E_F  1.4426950408889634f
#define LOG2PI_F 1.8378770664093453f
#define LN2SQ_F  0.4804530139182014f
#define KCOMP 8
#define TPB 256
#define ELEMS_PER_THREAD 4
#define ELEMS_PER_BLOCK (TPB * ELEMS_PER_THREAD)  // 1024

// ---- packed f32x2 helpers (sm_100+ 64-bit fp32 pipe) ----
__device__ __forceinline__ ull pk2(float a, float b) {
    ull r; asm("mov.b64 %0, {%1, %2};" : "=l"(r) : "f"(a), "f"(b)); return r;
}
__device__ __forceinline__ void upk2(ull v, float& a, float& b) {
    asm("mov.b64 {%0, %1}, %2;" : "=f"(a), "=f"(b) : "l"(v));
}
__device__ __forceinline__ ull add2(ull a, ull b) {
    ull r; asm("add.rn.f32x2 %0, %1, %2;" : "=l"(r) : "l"(a), "l"(b)); return r;
}
__device__ __forceinline__ ull fma2(ull a, ull b, ull c) {
    ull r; asm("fma.rn.f32x2 %0, %1, %2, %3;" : "=l"(r) : "l"(a), "l"(b), "l"(c)); return r;
}
__device__ __forceinline__ float ex2f_fast(float x) {
    float r; asm("ex2.approx.ftz.f32 %0, %1;" : "=f"(r) : "f"(x)); return r;
}
// volatile EX2: pins stream position so the two warp-variants keep their
// intentionally different MUFU phases.
__device__ __forceinline__ float ex2f_pinned(float x) {
    float r; asm volatile("ex2.approx.ftz.f32 %0, %1;" : "=f"(r) : "f"(x)); return r;
}
__device__ __forceinline__ ull ex2_pair_pinned(ull t) {
    float t0, t1; upk2(t, t0, t1);
    return pk2(ex2f_pinned(t0), ex2f_pinned(t1));
}
__device__ __forceinline__ float rcpf_fast(float x) {
    float r; asm("rcp.approx.ftz.f32 %0, %1;" : "=f"(r) : "f"(x)); return r;
}

__global__ __launch_bounds__(TPB) void gmm_hscore_kernel(
    const float4* __restrict__ x4,
    const float*  __restrict__ mean,
    const float*  __restrict__ logvar,
    const float*  __restrict__ logweight,
    float4*       __restrict__ out4)
{
    // Per-k packed constants, paired for LDS.128:
    //   sAB[k] = {a2, b2} ; sCV[k] = {c2, nvs2}
    __shared__ ulonglong2 sAB[KCOMP];
    __shared__ ulonglong2 sCV[KCOMP];

    const int t = threadIdx.x;
    if (t < KCOMP) {
        float lv = logvar[t];
        float mu = mean[t];
        float lw = logweight[t];
        float iv = ex2f_fast(-lv * LOG2E_F);           // exp(-lv) = 1/var
        float a  = -0.5f * iv * LOG2E_F;
        float b  = -2.0f * a * mu;
        float c  = fmaf(a, mu * mu, (lw - 0.5f * (lv + LOG2PI_F)) * LOG2E_F);
        float nvs = -iv * (1.0f / LN2SQ_F);
        sAB[t] = make_ulonglong2(pk2(a, a), pk2(b, b));
        sCV[t] = make_ulonglong2(pk2(c, c), pk2(nvs, nvs));
    }
    __syncthreads();

    const int base = blockIdx.x * TPB + t;   // in float4 units
    float4 xa = x4[base];

    ull X0 = pk2(xa.x, xa.y);
    ull X1 = pk2(xa.z, xa.w);

    const ull Z = pk2(0.0f, 0.0f);
    ull MP0 = Z, MP1 = Z, MD0 = Z, MD1 = Z, DD0 = Z, DD1 = Z;

    // Variant selector: groups of 4 warps (warps 0-3 -> A, 4-7 -> B) so each
    // SMSP (wid%4) hosts BOTH variants. A wid&1 split would segregate variants
    // onto disjoint SMSPs and defeat the purpose.
    const bool pipelined = ((t >> 7) & 1) != 0;

    if (!pipelined) {
        // ---- Variant A: EX2 issued immediately after its exponent ----
        #pragma unroll
        for (int k = 0; k < KCOMP; k++) {
            const ulonglong2 ab = sAB[k];
            const ulonglong2 cv = sCV[k];
            const ull a2 = ab.x, b2 = ab.y, c2 = cv.x, v2 = cv.y;

            ull H0 = fma2(a2, X0, b2);
            ull H1 = fma2(a2, X1, b2);
            ull T0 = fma2(H0, X0, c2);
            ull T1 = fma2(H1, X1, c2);
            ull P0 = ex2_pair_pinned(T0);
            ull P1 = ex2_pair_pinned(T1);
            ull S0 = fma2(a2, X0, H0);
            ull S1 = fma2(a2, X1, H1);
            MP0 = add2(MP0, P0);
            MP1 = add2(MP1, P1);
            MD0 = fma2(P0, S0, MD0);
            MD1 = fma2(P1, S1, MD1);
            ull U0 = fma2(S0, S0, v2);
            ull U1 = fma2(S1, S1, v2);
            DD0 = fma2(P0, U0, DD0);
            DD1 = fma2(P1, U1, DD1);
        }
    } else {
        // ---- Variant B: software-pipelined by one k. Accumulations of k-1
        // precede the EX2 issue of k, shifting MUFU bursts ~20 insts later
        // in the stream relative to variant A. Same math, same k order.
        ull pP0, pP1, pS0, pS1, pV;
        {
            const ulonglong2 ab = sAB[0];
            const ulonglong2 cv = sCV[0];
            ull H0 = fma2(ab.x, X0, ab.y);
            ull H1 = fma2(ab.x, X1, ab.y);
            ull T0 = fma2(H0, X0, cv.x);
            ull T1 = fma2(H1, X1, cv.x);
            pP0 = ex2_pair_pinned(T0);
            pP1 = ex2_pair_pinned(T1);
            pS0 = fma2(ab.x, X0, H0);
            pS1 = fma2(ab.x, X1, H1);
            pV  = cv.y;
        }
        #pragma unroll
        for (int k = 1; k < KCOMP; k++) {
            const ulonglong2 ab = sAB[k];
            const ulonglong2 cv = sCV[k];
            // accumulate k-1
            MP0 = add2(MP0, pP0);
            MP1 = add2(MP1, pP1);
            MD0 = fma2(pP0, pS0, MD0);
            MD1 = fma2(pP1, pS1, MD1);
            ull U0 = fma2(pS0, pS0, pV);
            ull U1 = fma2(pS1, pS1, pV);
            DD0 = fma2(pP0, U0, DD0);
            DD1 = fma2(pP1, U1, DD1);
            // compute k
            ull H0 = fma2(ab.x, X0, ab.y);
            ull H1 = fma2(ab.x, X1, ab.y);
            ull T0 = fma2(H0, X0, cv.x);
            ull T1 = fma2(H1, X1, cv.x);
            pP0 = ex2_pair_pinned(T0);
            pP1 = ex2_pair_pinned(T1);
            pS0 = fma2(ab.x, X0, H0);
            pS1 = fma2(ab.x, X1, H1);
            pV  = cv.y;
        }
        // drain k=7
        MP0 = add2(MP0, pP0);
        MP1 = add2(MP1, pP1);
        MD0 = fma2(pP0, pS0, MD0);
        MD1 = fma2(pP1, pS1, MD1);
        ull U0 = fma2(pS0, pS0, pV);
        ull U1 = fma2(pS1, pS1, pV);
        DD0 = fma2(pP0, U0, DD0);
        DD1 = fma2(pP1, U1, DD1);
    }

    // ---- epilogue: h = ln2^2 * ( -0.5*(md'/mp)^2 + dd'/mp ) ----
    float h[4];
    {
        float mp0, mp1, md0, md1, dd0, dd1;
        upk2(MP0, mp0, mp1); upk2(MD0, md0, md1); upk2(DD0, dd0, dd1);
        float r0 = rcpf_fast(mp0), r1 = rcpf_fast(mp1);
        float dl0 = md0 * r0,      dl1 = md1 * r1;
        h[0] = LN2SQ_F * fmaf(-0.5f * dl0, dl0, dd0 * r0);
        h[1] = LN2SQ_F * fmaf(-0.5f * dl1, dl1, dd1 * r1);
        upk2(MP1, mp0, mp1); upk2(MD1, md0, md1); upk2(DD1, dd0, dd1);
        r0 = rcpf_fast(mp0); r1 = rcpf_fast(mp1);
        dl0 = md0 * r0;      dl1 = md1 * r1;
        h[2] = LN2SQ_F * fmaf(-0.5f * dl0, dl0, dd0 * r0);
        h[3] = LN2SQ_F * fmaf(-0.5f * dl1, dl1, dd1 * r1);
    }

    out4[base] = make_float4(h[0], h[1], h[2], h[3]);
}

extern "C" void kernel_launch(void* const* d_in, const int* in_sizes, int n_in,
                              void* d_out, int out_size) {
    const float4* x4        = (const float4*)d_in[0];
    const float*  mean      = (const float*)d_in[1];
    const float*  logvar    = (const float*)d_in[2];
    const float*  logweight = (const float*)d_in[3];
    float4*       out4      = (float4*)d_out;

    int n = in_sizes[0];                      // 4194304, divisible by 1024
    int blocks = n / ELEMS_PER_BLOCK;         // 4096
    gmm_hscore_kernel<<<blocks, TPB>>>(x4, mean, logvar, logweight, out4);
}